// round 1
// baseline (speedup 1.0000x reference)
#include <cuda_runtime.h>

#define NN 500000
#define EE 2000000
#define GG 64
#define EPS 1e-5f

// ---------------- scratch (device globals; no allocs allowed) ----------------
__device__ __align__(16) int   g_deg[NN];
__device__ __align__(16) float g_dis[NN];
__device__ __align__(16) int   g_c[NN];
__device__ __align__(16) float g_S[NN * 9];
__device__ __align__(16) float g_h1[(size_t)NN * 64];
__device__ __align__(16) float g_agg2[(size_t)NN * 64];
__device__ __align__(16) float g_M1[9 * 64];
__device__ __align__(16) float g_a1[64];
__device__ __align__(16) float g_sh1[64];
__device__ __align__(16) float g_s1[64];
__device__ __align__(16) float g_q1[64];
__device__ __align__(16) float g_s2[64];
__device__ __align__(16) float g_q2[64];
__device__ __align__(16) float g_psum[GG * 64];
__device__ __align__(16) int   g_pmax[GG * 64];
__device__ __align__(16) int   g_pmin[GG * 64];
__device__                int   g_cnt[GG];

// ---------------- helpers ----------------
__device__ __forceinline__ void red_add_v4(float* p, float4 v) {
    asm volatile("red.global.add.v4.f32 [%0], {%1, %2, %3, %4};"
                 :: "l"(p), "f"(v.x), "f"(v.y), "f"(v.z), "f"(v.w) : "memory");
}

__device__ __forceinline__ void atomicMaxFloat(int* addr, float v) {
    if (v >= 0.0f) atomicMax(addr, __float_as_int(v));
    else           atomicMin((unsigned int*)addr, __float_as_uint(v));
}
__device__ __forceinline__ void atomicMinFloat(int* addr, float v) {
    if (v >= 0.0f) atomicMin(addr, __float_as_int(v));
    else           atomicMax((unsigned int*)addr, __float_as_uint(v));
}

// ---------------- small init (pool buffers, stats) ----------------
__global__ void k_small_init() {
    int i = blockIdx.x * blockDim.x + threadIdx.x;
    if (i < GG * 64) {                       // pmax = -inf
        g_pmax[i] = 0xFF800000;
        g_pmin[i] = 0x7F800000;
        g_psum[i] = 0.0f;
    }
    if (i < 64) {
        g_s1[i] = 0.0f; g_q1[i] = 0.0f;
        g_s2[i] = 0.0f; g_q2[i] = 0.0f;
    }
    if (i < GG) g_cnt[i] = 0;
}

// ---------------- M1 = [emb_type || emb_inv] @ W1  (9 x 64) ----------------
__global__ void k_prep(const float* __restrict__ emb_type,
                       const float* __restrict__ emb_inv,
                       const float* __restrict__ W1) {
    int t = threadIdx.x;
    if (t >= 9 * 64) return;
    int combo = t >> 6;      // 0..8
    int f = t & 63;
    int ty = combo / 3, iv = combo % 3;
    float acc = 0.0f;
#pragma unroll
    for (int k = 0; k < 16; k++) {
        acc = fmaf(emb_type[ty * 16 + k], W1[k * 64 + f], acc);
        acc = fmaf(emb_inv[iv * 16 + k], W1[(16 + k) * 64 + f], acc);
    }
    g_M1[combo * 64 + f] = acc;
}

// ---------------- degree histogram ----------------
__global__ void k_deg(const int* __restrict__ edst) {
    int e = blockIdx.x * blockDim.x + threadIdx.x;
    if (e < EE) atomicAdd(&g_deg[edst[e]], 1);
}

// ---------------- per-node: dis, combo idx, self-loop seed of S, graph counts --
__global__ void k_dis(const int* __restrict__ node_type,
                      const int* __restrict__ num_inv,
                      const int* __restrict__ batch) {
    int v = blockIdx.x * blockDim.x + threadIdx.x;
    if (v >= NN) return;
    int d = g_deg[v] + 1;                       // + self loop
    float dis = rsqrtf((float)d);
    g_dis[v] = dis;
    int c = node_type[v] * 3 + num_inv[v];
    g_c[v] = c;
    g_S[v * 9 + c] = dis * dis;                 // self-loop norm = 1/deg
    atomicAdd(&g_cnt[batch[v]], 1);
}

// ---------------- layer-1 bucket aggregation: 1 atomic per edge ----------------
__global__ void k_edge1(const int* __restrict__ esrc, const int* __restrict__ edst) {
    int e = blockIdx.x * blockDim.x + threadIdx.x;
    if (e >= EE) return;
    int s = esrc[e], d = edst[e];
    atomicAdd(&g_S[d * 9 + g_c[s]], g_dis[s] * g_dis[d]);
}

// ---------------- layer-1 transform: h1_pre = S @ M1, + BN1 stats ----------------
__global__ __launch_bounds__(256) void k_layer1() {
    __shared__ float sM1[9 * 64];
    __shared__ float sred[256];
    for (int i = threadIdx.x; i < 9 * 64; i += 256) sM1[i] = g_M1[i];
    __syncthreads();

    int lane = threadIdx.x & 31;
    int warp = (blockIdx.x * blockDim.x + threadIdx.x) >> 5;
    int nwarps = (gridDim.x * blockDim.x) >> 5;

    float a0 = 0.f, a1 = 0.f, qq0 = 0.f, qq1 = 0.f;
    for (int v = warp; v < NN; v += nwarps) {
        float y0 = 0.f, y1 = 0.f;
#pragma unroll
        for (int t = 0; t < 9; t++) {
            float sv = g_S[v * 9 + t];          // warp-broadcast load
            y0 = fmaf(sv, sM1[t * 64 + 2 * lane], y0);
            y1 = fmaf(sv, sM1[t * 64 + 2 * lane + 1], y1);
        }
        ((float2*)g_h1)[(size_t)v * 32 + lane] = make_float2(y0, y1);
        a0 += y0; a1 += y1; qq0 += y0 * y0; qq1 += y1 * y1;
    }

    float vals[4] = {a0, a1, qq0, qq1};
#pragma unroll
    for (int r = 0; r < 4; r++) {
        __syncthreads();
        sred[threadIdx.x] = vals[r];
        __syncthreads();
        if (threadIdx.x < 32) {
            float acc = 0.f;
#pragma unroll
            for (int w = 0; w < 8; w++) acc += sred[threadIdx.x + 32 * w];
            int f = 2 * threadIdx.x + (r & 1);
            if (r < 2) atomicAdd(&g_s1[f], acc);
            else       atomicAdd(&g_q1[f], acc);
        }
    }
}

// ---------------- BN1 affine params ----------------
__global__ void k_bn1(const float* __restrict__ gamma1, const float* __restrict__ beta1) {
    int f = threadIdx.x;
    if (f >= 64) return;
    float mu = g_s1[f] / (float)NN;
    float var = g_q1[f] / (float)NN - mu * mu;
    float a = rsqrtf(var + EPS) * gamma1[f];
    g_a1[f] = a;
    g_sh1[f] = beta1[f] - mu * a;
}

// ---------- layer-2 edge phase: gather h1_pre[src], BN1+relu on the fly,
// ---------- scale by norm, vector-reduce into agg2[dst]. Half-warp per edge. ----
__global__ __launch_bounds__(256) void k_edge2(const int* __restrict__ esrc,
                                               const int* __restrict__ edst) {
    int lane = threadIdx.x & 31;
    int half = lane >> 4;                 // which edge of the pair
    int k = lane & 15;                    // float4 chunk within the 64-dim row
    int gw = (blockIdx.x * blockDim.x + threadIdx.x) >> 5;
    int nw = (gridDim.x * blockDim.x) >> 5;

    float4 a1v = ((const float4*)g_a1)[k];
    float4 sh1v = ((const float4*)g_sh1)[k];

    for (int ep = gw; ep < EE / 2; ep += nw) {
        int e = 2 * ep + half;
        int s = esrc[e], d = edst[e];
        float norm = g_dis[s] * g_dis[d];
        float4 x = ((const float4*)(g_h1 + (size_t)s * 64))[k];
        float4 y;
        y.x = fmaxf(fmaf(x.x, a1v.x, sh1v.x), 0.f) * norm;
        y.y = fmaxf(fmaf(x.y, a1v.y, sh1v.y), 0.f) * norm;
        y.z = fmaxf(fmaf(x.z, a1v.z, sh1v.z), 0.f) * norm;
        y.w = fmaxf(fmaf(x.w, a1v.w, sh1v.w), 0.f) * norm;
        red_add_v4(g_agg2 + (size_t)d * 64 + 4 * k, y);
    }
}

// ---------- layer-2 GEMM + BN2 stats + fused graph pooling ----------
// val[v] = agg2[v] + (1/deg)*relu(affine1(h1_pre[v]));  y = val @ W2.
// y is never stored: reduced into per-graph max/min/sum + global sum/sumsq.
#define TN 128
#define NB2 512
__global__ __launch_bounds__(256, 2) void k_layer2pool(const int* __restrict__ batch,
                                                       const float* __restrict__ W2) {
    __shared__ float4 As4[TN * 16];   // 32 KB  [node][k/4]
    __shared__ float4 Bs4[64 * 16];   // 16 KB  [k][f/4]
    int tid = threadIdx.x;
    int tf = tid & 15;                // feature group (4 feats)
    int tn = tid >> 4;                // node group   (8 nodes in GEMM stage)

    for (int i = tid; i < 1024; i += 256) Bs4[i] = ((const float4*)W2)[i];

    float4 a1v = ((const float4*)g_a1)[tf];
    float4 sh1v = ((const float4*)g_sh1)[tf];

    float psum[4] = {0, 0, 0, 0};
    float pmx[4], pmn[4];
#pragma unroll
    for (int j = 0; j < 4; j++) { pmx[j] = -__int_as_float(0x7F800000); pmn[j] = __int_as_float(0x7F800000); }
    int gcur = -1;
    float ss[4] = {0, 0, 0, 0}, sq[4] = {0, 0, 0, 0};

    int tiles = (NN + TN - 1) / TN;
    int tpb = (tiles + NB2 - 1) / NB2;
    int t0 = blockIdx.x * tpb;
    int t1 = min(t0 + tpb, tiles);

    for (int t = t0; t < t1; t++) {
        int base = t * TN;
        __syncthreads();   // protect As from previous tile's GEMM readers
        // ---- stage 1: build input tile (coalesced) ----
#pragma unroll
        for (int kb = 0; kb < 8; kb++) {
            int nl = tn + 16 * kb;
            int v = base + nl;
            float4 val = {0.f, 0.f, 0.f, 0.f};
            if (v < NN) {
                float4 ag = ((const float4*)g_agg2)[(size_t)v * 16 + tf];
                float4 h  = ((const float4*)g_h1)[(size_t)v * 16 + tf];
                float dd = g_dis[v];
                float id = dd * dd;
                val.x = fmaf(id, fmaxf(fmaf(h.x, a1v.x, sh1v.x), 0.f), ag.x);
                val.y = fmaf(id, fmaxf(fmaf(h.y, a1v.y, sh1v.y), 0.f), ag.y);
                val.z = fmaf(id, fmaxf(fmaf(h.z, a1v.z, sh1v.z), 0.f), ag.z);
                val.w = fmaf(id, fmaxf(fmaf(h.w, a1v.w, sh1v.w), 0.f), ag.w);
            }
            As4[nl * 16 + tf] = val;
        }
        __syncthreads();

        // ---- stage 2: register-tiled GEMM (8 nodes x 4 feats per thread) ----
        float4 acc[8];
#pragma unroll
        for (int i = 0; i < 8; i++) acc[i] = make_float4(0.f, 0.f, 0.f, 0.f);
#pragma unroll 4
        for (int kk = 0; kk < 16; kk++) {
            float4 b0 = Bs4[(4 * kk + 0) * 16 + tf];
            float4 b1 = Bs4[(4 * kk + 1) * 16 + tf];
            float4 b2 = Bs4[(4 * kk + 2) * 16 + tf];
            float4 b3 = Bs4[(4 * kk + 3) * 16 + tf];
#pragma unroll
            for (int i = 0; i < 8; i++) {
                float4 a = As4[(tn * 8 + i) * 16 + kk];
                acc[i].x = fmaf(a.x, b0.x, fmaf(a.y, b1.x, fmaf(a.z, b2.x, fmaf(a.w, b3.x, acc[i].x))));
                acc[i].y = fmaf(a.x, b0.y, fmaf(a.y, b1.y, fmaf(a.z, b2.y, fmaf(a.w, b3.y, acc[i].y))));
                acc[i].z = fmaf(a.x, b0.z, fmaf(a.y, b1.z, fmaf(a.z, b2.z, fmaf(a.w, b3.z, acc[i].z))));
                acc[i].w = fmaf(a.x, b0.w, fmaf(a.y, b1.w, fmaf(a.z, b2.w, fmaf(a.w, b3.w, acc[i].w))));
            }
        }

        // ---- stage 3: epilogue — per-graph running reduce (batch is sorted) ----
#pragma unroll
        for (int i = 0; i < 8; i++) {
            int v = base + tn * 8 + i;
            if (v >= NN) break;
            int g = batch[v];
            if (g != gcur) {
                if (gcur >= 0) {
                    int pb = gcur * 64 + tf * 4;
#pragma unroll
                    for (int j = 0; j < 4; j++) {
                        atomicAdd(&g_psum[pb + j], psum[j]);
                        atomicMaxFloat(&g_pmax[pb + j], pmx[j]);
                        atomicMinFloat(&g_pmin[pb + j], pmn[j]);
                    }
                }
                gcur = g;
#pragma unroll
                for (int j = 0; j < 4; j++) {
                    psum[j] = 0.f;
                    pmx[j] = -__int_as_float(0x7F800000);
                    pmn[j] = __int_as_float(0x7F800000);
                }
            }
            float y[4] = {acc[i].x, acc[i].y, acc[i].z, acc[i].w};
#pragma unroll
            for (int j = 0; j < 4; j++) {
                psum[j] += y[j];
                pmx[j] = fmaxf(pmx[j], y[j]);
                pmn[j] = fminf(pmn[j], y[j]);
                ss[j] += y[j];
                sq[j] = fmaf(y[j], y[j], sq[j]);
            }
        }
    }
    // final flushes
    if (gcur >= 0) {
        int pb = gcur * 64 + tf * 4;
#pragma unroll
        for (int j = 0; j < 4; j++) {
            atomicAdd(&g_psum[pb + j], psum[j]);
            atomicMaxFloat(&g_pmax[pb + j], pmx[j]);
            atomicMinFloat(&g_pmin[pb + j], pmn[j]);
        }
    }
#pragma unroll
    for (int j = 0; j < 4; j++) {
        atomicAdd(&g_s2[tf * 4 + j], ss[j]);
        atomicAdd(&g_q2[tf * 4 + j], sq[j]);
    }
}

// ---------------- finalize: BN2 affine applied to pooled raw values ----------------
__global__ void k_final(const float* __restrict__ gamma2, const float* __restrict__ beta2,
                        float* __restrict__ out) {
    int f = threadIdx.x;
    if (f >= 64) return;
    float mu = g_s2[f] / (float)NN;
    float var = g_q2[f] / (float)NN - mu * mu;
    float a = rsqrtf(var + EPS) * gamma2[f];
    float sh = beta2[f] - mu * a;
    for (int g = 0; g < GG; g++) {
        float mx = __int_as_float(g_pmax[g * 64 + f]);
        float mn = __int_as_float(g_pmin[g * 64 + f]);
        float chosen = (a >= 0.f) ? mx : mn;            // max commutes with monotone affine
        out[g * 128 + f] = fmaf(chosen, a, sh);
        float c = fmaxf((float)g_cnt[g], 1.f);
        out[g * 128 + 64 + f] = fmaf(g_psum[g * 64 + f] / c, a, sh);
    }
}

// ---------------- launch ----------------
extern "C" void kernel_launch(void* const* d_in, const int* in_sizes, int n_in,
                              void* d_out, int out_size) {
    const int* node_type = (const int*)d_in[0];
    const int* num_inv   = (const int*)d_in[1];
    const int* edge      = (const int*)d_in[2];
    const int* batch     = (const int*)d_in[3];
    const float* emb_type = (const float*)d_in[4];
    const float* emb_inv  = (const float*)d_in[5];
    const float* W1       = (const float*)d_in[6];
    const float* W2       = (const float*)d_in[8];
    const float* gamma1   = (const float*)d_in[10];
    const float* beta1    = (const float*)d_in[11];
    const float* gamma2   = (const float*)d_in[12];
    const float* beta2    = (const float*)d_in[13];
    float* out = (float*)d_out;

    const int* esrc = edge;
    const int* edst = edge + EE;

    void *pDeg, *pS, *pAgg;
    cudaGetSymbolAddress(&pDeg, g_deg);
    cudaGetSymbolAddress(&pS, g_S);
    cudaGetSymbolAddress(&pAgg, g_agg2);
    cudaMemsetAsync(pDeg, 0, (size_t)NN * sizeof(int));
    cudaMemsetAsync(pS, 0, (size_t)NN * 9 * sizeof(float));
    cudaMemsetAsync(pAgg, 0, (size_t)NN * 64 * sizeof(float));

    k_small_init<<<(GG * 64 + 255) / 256, 256>>>();
    k_prep<<<1, 576>>>(emb_type, emb_inv, W1);
    k_deg<<<(EE + 255) / 256, 256>>>(edst);
    k_dis<<<(NN + 255) / 256, 256>>>(node_type, num_inv, batch);
    k_edge1<<<(EE + 255) / 256, 256>>>(esrc, edst);
    k_layer1<<<1184, 256>>>();
    k_bn1<<<1, 64>>>(gamma1, beta1);
    k_edge2<<<1184, 256>>>(esrc, edst);
    k_layer2pool<<<NB2, 256>>>(batch, W2);
    k_final<<<1, 64>>>(gamma2, beta2, out);
}

// round 2
// speedup vs baseline: 1.4361x; 1.4361x over previous
#include <cuda_runtime.h>

#define NN 500000
#define EE 2000000
#define GG 64
#define EPS 1e-5f

// ---------------- scratch (device globals; no allocs allowed) ----------------
__device__ __align__(16) int   g_deg[NN];
__device__ __align__(16) float g_dis[NN];
__device__ __align__(16) int   g_c[NN];
__device__ __align__(16) float g_S[NN * 9];
__device__ __align__(16) float g_h1[(size_t)NN * 64];
__device__ __align__(16) float g_agg2[(size_t)NN * 64];
__device__ __align__(16) float g_M1[9 * 64];
__device__ __align__(16) float g_a1[64];
__device__ __align__(16) float g_sh1[64];
__device__ __align__(16) float g_s1[64];
__device__ __align__(16) float g_q1[64];
__device__ __align__(16) float g_s2[64];
__device__ __align__(16) float g_q2[64];
__device__ __align__(16) float g_psum[GG * 64];
__device__ __align__(16) int   g_pmax[GG * 64];
__device__ __align__(16) int   g_pmin[GG * 64];
__device__                int   g_cnt[GG];

// ---------------- helpers ----------------
__device__ __forceinline__ void red_add_v4(float* p, float4 v) {
    asm volatile("red.global.add.v4.f32 [%0], {%1, %2, %3, %4};"
                 :: "l"(p), "f"(v.x), "f"(v.y), "f"(v.z), "f"(v.w) : "memory");
}

__device__ __forceinline__ void atomicMaxFloat(int* addr, float v) {
    if (v >= 0.0f) atomicMax(addr, __float_as_int(v));
    else           atomicMin((unsigned int*)addr, __float_as_uint(v));
}
__device__ __forceinline__ void atomicMinFloat(int* addr, float v) {
    if (v >= 0.0f) atomicMin(addr, __float_as_int(v));
    else           atomicMax((unsigned int*)addr, __float_as_uint(v));
}

// ---------------- small init (pool buffers, stats) ----------------
__global__ void k_small_init() {
    int i = blockIdx.x * blockDim.x + threadIdx.x;
    if (i < GG * 64) {                       // pmax = -inf
        g_pmax[i] = 0xFF800000;
        g_pmin[i] = 0x7F800000;
        g_psum[i] = 0.0f;
    }
    if (i < 64) {
        g_s1[i] = 0.0f; g_q1[i] = 0.0f;
        g_s2[i] = 0.0f; g_q2[i] = 0.0f;
    }
}

// ---------------- per-graph node counts: binary search over sorted batch -----
__global__ void k_cnt(const int* __restrict__ batch) {
    int g = threadIdx.x;
    if (g >= GG) return;
    // lower_bound(batch, g) and lower_bound(batch, g+1)
    int lo0 = 0, hi0 = NN;
    while (lo0 < hi0) { int m = (lo0 + hi0) >> 1; if (batch[m] < g) lo0 = m + 1; else hi0 = m; }
    int lo1 = lo0, hi1 = NN;
    while (lo1 < hi1) { int m = (lo1 + hi1) >> 1; if (batch[m] < g + 1) lo1 = m + 1; else hi1 = m; }
    g_cnt[g] = lo1 - lo0;
}

// ---------------- M1 = [emb_type || emb_inv] @ W1  (9 x 64) ----------------
__global__ void k_prep(const float* __restrict__ emb_type,
                       const float* __restrict__ emb_inv,
                       const float* __restrict__ W1) {
    int t = threadIdx.x;
    if (t >= 9 * 64) return;
    int combo = t >> 6;      // 0..8
    int f = t & 63;
    int ty = combo / 3, iv = combo % 3;
    float acc = 0.0f;
#pragma unroll
    for (int k = 0; k < 16; k++) {
        acc = fmaf(emb_type[ty * 16 + k], W1[k * 64 + f], acc);
        acc = fmaf(emb_inv[iv * 16 + k], W1[(16 + k) * 64 + f], acc);
    }
    g_M1[combo * 64 + f] = acc;
}

// ---------------- degree histogram ----------------
__global__ void k_deg(const int* __restrict__ edst) {
    int e = blockIdx.x * blockDim.x + threadIdx.x;
    if (e < EE) atomicAdd(&g_deg[edst[e]], 1);
}

// ---------------- per-node: dis, combo idx, self-loop seed of S ----------------
__global__ void k_dis(const int* __restrict__ node_type,
                      const int* __restrict__ num_inv) {
    int v = blockIdx.x * blockDim.x + threadIdx.x;
    if (v >= NN) return;
    int d = g_deg[v] + 1;                       // + self loop
    float dis = rsqrtf((float)d);
    g_dis[v] = dis;
    int c = node_type[v] * 3 + num_inv[v];
    g_c[v] = c;
    g_S[v * 9 + c] = dis * dis;                 // self-loop norm = 1/deg
}

// ---------------- layer-1 bucket aggregation: 1 atomic per edge ----------------
__global__ void k_edge1(const int* __restrict__ esrc, const int* __restrict__ edst) {
    int e = blockIdx.x * blockDim.x + threadIdx.x;
    if (e >= EE) return;
    int s = esrc[e], d = edst[e];
    atomicAdd(&g_S[d * 9 + g_c[s]], g_dis[s] * g_dis[d]);
}

// ---------------- layer-1 transform: h1_pre = S @ M1, + BN1 stats ----------------
__global__ __launch_bounds__(256) void k_layer1() {
    __shared__ float sM1[9 * 64];
    __shared__ float sred[256];
    for (int i = threadIdx.x; i < 9 * 64; i += 256) sM1[i] = g_M1[i];
    __syncthreads();

    int lane = threadIdx.x & 31;
    int warp = (blockIdx.x * blockDim.x + threadIdx.x) >> 5;
    int nwarps = (gridDim.x * blockDim.x) >> 5;

    float a0 = 0.f, a1 = 0.f, qq0 = 0.f, qq1 = 0.f;
    for (int v = warp; v < NN; v += nwarps) {
        float y0 = 0.f, y1 = 0.f;
#pragma unroll
        for (int t = 0; t < 9; t++) {
            float sv = g_S[v * 9 + t];          // warp-broadcast load
            y0 = fmaf(sv, sM1[t * 64 + 2 * lane], y0);
            y1 = fmaf(sv, sM1[t * 64 + 2 * lane + 1], y1);
        }
        ((float2*)g_h1)[(size_t)v * 32 + lane] = make_float2(y0, y1);
        a0 += y0; a1 += y1; qq0 += y0 * y0; qq1 += y1 * y1;
    }

    float vals[4] = {a0, a1, qq0, qq1};
#pragma unroll
    for (int r = 0; r < 4; r++) {
        __syncthreads();
        sred[threadIdx.x] = vals[r];
        __syncthreads();
        if (threadIdx.x < 32) {
            float acc = 0.f;
#pragma unroll
            for (int w = 0; w < 8; w++) acc += sred[threadIdx.x + 32 * w];
            int f = 2 * threadIdx.x + (r & 1);
            if (r < 2) atomicAdd(&g_s1[f], acc);
            else       atomicAdd(&g_q1[f], acc);
        }
    }
}

// ---------------- BN1 affine params ----------------
__global__ void k_bn1(const float* __restrict__ gamma1, const float* __restrict__ beta1) {
    int f = threadIdx.x;
    if (f >= 64) return;
    float mu = g_s1[f] / (float)NN;
    float var = g_q1[f] / (float)NN - mu * mu;
    float a = rsqrtf(var + EPS) * gamma1[f];
    g_a1[f] = a;
    g_sh1[f] = beta1[f] - mu * a;
}

// ---------- layer-2 edge phase: gather h1_pre[src], BN1+relu on the fly,
// ---------- scale by norm, vector-reduce into agg2[dst]. Half-warp per edge. ----
__global__ __launch_bounds__(256) void k_edge2(const int* __restrict__ esrc,
                                               const int* __restrict__ edst) {
    int lane = threadIdx.x & 31;
    int half = lane >> 4;                 // which edge of the pair
    int k = lane & 15;                    // float4 chunk within the 64-dim row
    int gw = (blockIdx.x * blockDim.x + threadIdx.x) >> 5;
    int nw = (gridDim.x * blockDim.x) >> 5;

    float4 a1v = ((const float4*)g_a1)[k];
    float4 sh1v = ((const float4*)g_sh1)[k];

    for (int ep = gw; ep < EE / 2; ep += nw) {
        int e = 2 * ep + half;
        int s = esrc[e], d = edst[e];
        float norm = g_dis[s] * g_dis[d];
        float4 x = ((const float4*)(g_h1 + (size_t)s * 64))[k];
        float4 y;
        y.x = fmaxf(fmaf(x.x, a1v.x, sh1v.x), 0.f) * norm;
        y.y = fmaxf(fmaf(x.y, a1v.y, sh1v.y), 0.f) * norm;
        y.z = fmaxf(fmaf(x.z, a1v.z, sh1v.z), 0.f) * norm;
        y.w = fmaxf(fmaf(x.w, a1v.w, sh1v.w), 0.f) * norm;
        red_add_v4(g_agg2 + (size_t)d * 64 + 4 * k, y);
    }
}

// ---------- layer-2 GEMM + BN2 stats + fused graph pooling ----------
// val[v] = agg2[v] + (1/deg)*relu(affine1(h1_pre[v]));  y = val @ W2.
// y is never stored: reduced into per-graph max/min/sum + global sum/sumsq.
#define TN 128
#define NB2 512
__global__ __launch_bounds__(256, 2) void k_layer2pool(const int* __restrict__ batch,
                                                       const float* __restrict__ W2) {
    __shared__ float4 As4[TN * 16];   // 32 KB  [node][k/4]
    __shared__ float4 Bs4[64 * 16];   // 16 KB  [k][f/4]
    int tid = threadIdx.x;
    int tf = tid & 15;                // feature group (4 feats)
    int tn = tid >> 4;                // node group   (8 nodes in GEMM stage)

    for (int i = tid; i < 1024; i += 256) Bs4[i] = ((const float4*)W2)[i];

    float4 a1v = ((const float4*)g_a1)[tf];
    float4 sh1v = ((const float4*)g_sh1)[tf];

    float psum[4] = {0, 0, 0, 0};
    float pmx[4], pmn[4];
#pragma unroll
    for (int j = 0; j < 4; j++) { pmx[j] = -__int_as_float(0x7F800000); pmn[j] = __int_as_float(0x7F800000); }
    int gcur = -1;
    float ss[4] = {0, 0, 0, 0}, sq[4] = {0, 0, 0, 0};

    int tiles = (NN + TN - 1) / TN;
    int tpb = (tiles + NB2 - 1) / NB2;
    int t0 = blockIdx.x * tpb;
    int t1 = min(t0 + tpb, tiles);

    for (int t = t0; t < t1; t++) {
        int base = t * TN;
        __syncthreads();   // protect As from previous tile's GEMM readers
        // ---- stage 1: build input tile (coalesced) ----
#pragma unroll
        for (int kb = 0; kb < 8; kb++) {
            int nl = tn + 16 * kb;
            int v = base + nl;
            float4 val = {0.f, 0.f, 0.f, 0.f};
            if (v < NN) {
                float4 ag = ((const float4*)g_agg2)[(size_t)v * 16 + tf];
                float4 h  = ((const float4*)g_h1)[(size_t)v * 16 + tf];
                float dd = g_dis[v];
                float id = dd * dd;
                val.x = fmaf(id, fmaxf(fmaf(h.x, a1v.x, sh1v.x), 0.f), ag.x);
                val.y = fmaf(id, fmaxf(fmaf(h.y, a1v.y, sh1v.y), 0.f), ag.y);
                val.z = fmaf(id, fmaxf(fmaf(h.z, a1v.z, sh1v.z), 0.f), ag.z);
                val.w = fmaf(id, fmaxf(fmaf(h.w, a1v.w, sh1v.w), 0.f), ag.w);
            }
            As4[nl * 16 + tf] = val;
        }
        __syncthreads();

        // ---- stage 2: register-tiled GEMM (8 nodes x 4 feats per thread) ----
        float4 acc[8];
#pragma unroll
        for (int i = 0; i < 8; i++) acc[i] = make_float4(0.f, 0.f, 0.f, 0.f);
#pragma unroll 4
        for (int kk = 0; kk < 16; kk++) {
            float4 b0 = Bs4[(4 * kk + 0) * 16 + tf];
            float4 b1 = Bs4[(4 * kk + 1) * 16 + tf];
            float4 b2 = Bs4[(4 * kk + 2) * 16 + tf];
            float4 b3 = Bs4[(4 * kk + 3) * 16 + tf];
#pragma unroll
            for (int i = 0; i < 8; i++) {
                float4 a = As4[(tn * 8 + i) * 16 + kk];
                acc[i].x = fmaf(a.x, b0.x, fmaf(a.y, b1.x, fmaf(a.z, b2.x, fmaf(a.w, b3.x, acc[i].x))));
                acc[i].y = fmaf(a.x, b0.y, fmaf(a.y, b1.y, fmaf(a.z, b2.y, fmaf(a.w, b3.y, acc[i].y))));
                acc[i].z = fmaf(a.x, b0.z, fmaf(a.y, b1.z, fmaf(a.z, b2.z, fmaf(a.w, b3.z, acc[i].z))));
                acc[i].w = fmaf(a.x, b0.w, fmaf(a.y, b1.w, fmaf(a.z, b2.w, fmaf(a.w, b3.w, acc[i].w))));
            }
        }

        // ---- stage 3: epilogue — per-graph running reduce (batch is sorted) ----
#pragma unroll
        for (int i = 0; i < 8; i++) {
            int v = base + tn * 8 + i;
            if (v >= NN) break;
            int g = batch[v];
            if (g != gcur) {
                if (gcur >= 0) {
                    int pb = gcur * 64 + tf * 4;
#pragma unroll
                    for (int j = 0; j < 4; j++) {
                        atomicAdd(&g_psum[pb + j], psum[j]);
                        atomicMaxFloat(&g_pmax[pb + j], pmx[j]);
                        atomicMinFloat(&g_pmin[pb + j], pmn[j]);
                    }
                }
                gcur = g;
#pragma unroll
                for (int j = 0; j < 4; j++) {
                    psum[j] = 0.f;
                    pmx[j] = -__int_as_float(0x7F800000);
                    pmn[j] = __int_as_float(0x7F800000);
                }
            }
            float y[4] = {acc[i].x, acc[i].y, acc[i].z, acc[i].w};
#pragma unroll
            for (int j = 0; j < 4; j++) {
                psum[j] += y[j];
                pmx[j] = fmaxf(pmx[j], y[j]);
                pmn[j] = fminf(pmn[j], y[j]);
                ss[j] += y[j];
                sq[j] = fmaf(y[j], y[j], sq[j]);
            }
        }
    }
    // final flushes
    if (gcur >= 0) {
        int pb = gcur * 64 + tf * 4;
#pragma unroll
        for (int j = 0; j < 4; j++) {
            atomicAdd(&g_psum[pb + j], psum[j]);
            atomicMaxFloat(&g_pmax[pb + j], pmx[j]);
            atomicMinFloat(&g_pmin[pb + j], pmn[j]);
        }
    }
#pragma unroll
    for (int j = 0; j < 4; j++) {
        atomicAdd(&g_s2[tf * 4 + j], ss[j]);
        atomicAdd(&g_q2[tf * 4 + j], sq[j]);
    }
}

// ---------------- finalize: BN2 affine applied to pooled raw values ----------------
__global__ void k_final(const float* __restrict__ gamma2, const float* __restrict__ beta2,
                        float* __restrict__ out) {
    int f = threadIdx.x;
    if (f >= 64) return;
    float mu = g_s2[f] / (float)NN;
    float var = g_q2[f] / (float)NN - mu * mu;
    float a = rsqrtf(var + EPS) * gamma2[f];
    float sh = beta2[f] - mu * a;
    for (int g = 0; g < GG; g++) {
        float mx = __int_as_float(g_pmax[g * 64 + f]);
        float mn = __int_as_float(g_pmin[g * 64 + f]);
        float chosen = (a >= 0.f) ? mx : mn;            // max commutes with monotone affine
        out[g * 128 + f] = fmaf(chosen, a, sh);
        float c = fmaxf((float)g_cnt[g], 1.f);
        out[g * 128 + 64 + f] = fmaf(g_psum[g * 64 + f] / c, a, sh);
    }
}

// ---------------- launch ----------------
extern "C" void kernel_launch(void* const* d_in, const int* in_sizes, int n_in,
                              void* d_out, int out_size) {
    const int* node_type = (const int*)d_in[0];
    const int* num_inv   = (const int*)d_in[1];
    const int* edge      = (const int*)d_in[2];
    const int* batch     = (const int*)d_in[3];
    const float* emb_type = (const float*)d_in[4];
    const float* emb_inv  = (const float*)d_in[5];
    const float* W1       = (const float*)d_in[6];
    const float* W2       = (const float*)d_in[8];
    const float* gamma1   = (const float*)d_in[10];
    const float* beta1    = (const float*)d_in[11];
    const float* gamma2   = (const float*)d_in[12];
    const float* beta2    = (const float*)d_in[13];
    float* out = (float*)d_out;

    const int* esrc = edge;
    const int* edst = edge + EE;

    void *pDeg, *pS, *pAgg;
    cudaGetSymbolAddress(&pDeg, g_deg);
    cudaGetSymbolAddress(&pS, g_S);
    cudaGetSymbolAddress(&pAgg, g_agg2);
    cudaMemsetAsync(pDeg, 0, (size_t)NN * sizeof(int));
    cudaMemsetAsync(pS, 0, (size_t)NN * 9 * sizeof(float));
    cudaMemsetAsync(pAgg, 0, (size_t)NN * 64 * sizeof(float));

    k_small_init<<<(GG * 64 + 255) / 256, 256>>>();
    k_cnt<<<1, 64>>>(batch);
    k_prep<<<1, 576>>>(emb_type, emb_inv, W1);
    k_deg<<<(EE + 255) / 256, 256>>>(edst);
    k_dis<<<(NN + 255) / 256, 256>>>(node_type, num_inv);
    k_edge1<<<(EE + 255) / 256, 256>>>(esrc, edst);
    k_layer1<<<1184, 256>>>();
    k_bn1<<<1, 64>>>(gamma1, beta1);
    k_edge2<<<1184, 256>>>(esrc, edst);
    k_layer2pool<<<NB2, 256>>>(batch, W2);
    k_final<<<1, 64>>>(gamma2, beta2, out);
}